// round 2
// baseline (speedup 1.0000x reference)
#include <cuda_runtime.h>

// FuzzyNeuron: out[n] = sum_r z[n,r]*w[n,r] / (sum_r w[n,r] + 1e-13)
//   z[n,r]    = dot(x[n], rho[r,:A]) + rho[r,A]
//   logw[n,r] = sum_a (q[r,a]*x^2 + b[r,a]*x) + f[r]
//     with q = -1/(2s^2), b = mu/s^2, f = -sum_a mu^2/(2s^2)
//
// R2 strategy: occupancy fix. 1 row/thread, f32x2 packed over FEATURE PAIRS
// (a=2p, 2p+1) instead of row pairs -> 131072 threads (28 warps/SM) vs 32768
// (7 warps/SM). Same packed-FMA count, 4x the latency hiding.

#define A_DIM 16
#define A_PAIRS 8
#define R_RULES 64
#define BLOCK 256

typedef unsigned long long u64;

__device__ __forceinline__ u64 pack2(float lo, float hi) {
    u64 r;
    asm("mov.b64 %0, {%1, %2};" : "=l"(r) : "f"(lo), "f"(hi));
    return r;
}
__device__ __forceinline__ void unpack2(float& lo, float& hi, u64 v) {
    asm("mov.b64 {%0, %1}, %2;" : "=f"(lo), "=f"(hi) : "l"(v));
}
__device__ __forceinline__ u64 fma2(u64 a, u64 b, u64 c) {
    u64 d;
    asm("fma.rn.f32x2 %0, %1, %2, %3;" : "=l"(d) : "l"(a), "l"(b), "l"(c));
    return d;
}

__global__ void __launch_bounds__(BLOCK)
fuzzy_neuron_kernel(const float* __restrict__ x,
                    const float* __restrict__ mu,
                    const float* __restrict__ sigma,
                    const float* __restrict__ rho,
                    float* __restrict__ out,
                    int n_rows) {
    // Packed coefficient tables (feature-pair layout, LDS.128/LDS.64 friendly):
    //   sQB [r][p] = {q_{2p}, q_{2p+1}, b_{2p}, b_{2p+1}}   (float4, 16B)
    //   sRho[r][p] = {rho_{2p}, rho_{2p+1}}                 (float2,  8B)
    //   sBF [r]    = {bias_r, f_r}                          (float2,  8B)
    __shared__ float4 sQB[R_RULES * A_PAIRS];   // 8 KB
    __shared__ float2 sRho[R_RULES * A_PAIRS];  // 4 KB
    __shared__ float2 sBF[R_RULES];             // 512 B

    const int tid = threadIdx.x;

    // ---- coefficient setup (per block; mu/sigma/rho are L2-resident) ----
    for (int idx = tid; idx < R_RULES * A_PAIRS; idx += BLOCK) {
        int r = idx >> 3;
        int p = idx & (A_PAIRS - 1);
        int a0 = 2 * p;
        float m0 = mu[r * A_DIM + a0],     s0 = sigma[r * A_DIM + a0];
        float m1 = mu[r * A_DIM + a0 + 1], s1 = sigma[r * A_DIM + a0 + 1];
        float c0 = 1.0f / (2.0f * s0 * s0);
        float c1 = 1.0f / (2.0f * s1 * s1);
        sQB[idx] = make_float4(-c0, -c1, 2.0f * c0 * m0, 2.0f * c1 * m1);
        sRho[idx] = make_float2(rho[r * (A_DIM + 1) + a0],
                                rho[r * (A_DIM + 1) + a0 + 1]);
    }
    for (int r = tid; r < R_RULES; r += BLOCK) {
        float f = 0.0f;
        for (int a = 0; a < A_DIM; a++) {
            float m = mu[r * A_DIM + a];
            float s = sigma[r * A_DIM + a];
            f -= (m * m) / (2.0f * s * s);
        }
        sBF[r] = make_float2(rho[r * (A_DIM + 1) + A_DIM], f);
    }
    __syncthreads();

    const int gid = blockIdx.x * BLOCK + tid;
    if (gid >= n_rows) return;

    // Load this row (4x float4 = 2 LDG.128) and pack into 8 feature pairs.
    const float4* x4 = reinterpret_cast<const float4*>(x);
    u64 xp[A_PAIRS];
#pragma unroll
    for (int j = 0; j < 4; j++) {
        float4 v = x4[gid * 4 + j];
        xp[2 * j + 0] = pack2(v.x, v.y);
        xp[2 * j + 1] = pack2(v.z, v.w);
    }

    float num = 0.0f, den = 0.0f;

    const float4* qb = sQB;
    const float2* rp = sRho;

#pragma unroll 2
    for (int r = 0; r < R_RULES; r++) {
        float2 bf = sBF[r];
        u64 lp = 0ULL, zp = 0ULL;
#pragma unroll
        for (int p = 0; p < A_PAIRS; p++) {
            float4 c = qb[p];                       // LDS.128 broadcast
            float2 rr = rp[p];                      // LDS.64  broadcast
            u64 q2 = pack2(c.x, c.y);
            u64 b2 = pack2(c.z, c.w);
            u64 r2 = pack2(rr.x, rr.y);
            u64 t = fma2(xp[p], q2, b2);            // q*x + b
            lp = fma2(xp[p], t, lp);                // += q*x^2 + b*x
            zp = fma2(xp[p], r2, zp);               // += rho*x
        }
        qb += A_PAIRS;
        rp += A_PAIRS;

        float l0, l1, z0, z1;
        unpack2(l0, l1, lp);   // register aliasing: free in SASS
        unpack2(z0, z1, zp);
        float logw = l0 + l1 + bf.y;
        float z = z0 + z1 + bf.x;
        float w = __expf(logw);
        num = fmaf(z, w, num);
        den += w;
    }

    out[gid] = num / (den + 1e-13f);
}

extern "C" void kernel_launch(void* const* d_in, const int* in_sizes, int n_in,
                              void* d_out, int out_size) {
    const float* x = (const float*)d_in[0];      // [N, 16]
    const float* mu = (const float*)d_in[1];     // [64, 16]
    const float* sigma = (const float*)d_in[2];  // [64, 16]
    const float* rho = (const float*)d_in[3];    // [64, 17]
    float* out = (float*)d_out;                  // [N]

    const int n_rows = in_sizes[0] / A_DIM;      // 131072
    const int blocks = (n_rows + BLOCK - 1) / BLOCK;

    fuzzy_neuron_kernel<<<blocks, BLOCK>>>(x, mu, sigma, rho, out, n_rows);
}

// round 3
// speedup vs baseline: 1.1311x; 1.1311x over previous
#include <cuda_runtime.h>

// FuzzyNeuron: out[n] = sum_r z[n,r]*w[n,r] / (sum_r w[n,r] + 1e-13)
//   z[n,r]    = dot(x[n], rho[r,:A]) + rho[r,A]
//   logw[n,r] = sum_a (q*x^2 + b*x) + f,  q=-1/(2s^2), b=mu/s^2, f=-sum mu^2/(2s^2)
//
// R3: FMA2-pipe-bound design.
//  - f32x2 packed over feature pairs (keeps FMA2 count at the 21K-cyc/SMSP floor)
//  - 2 rows/thread: halves per-rule LDS instruction count (R2's co-binder,
//    L1 was 66%) while keeping 512 CTAs (single full wave, ~28 warps/SM)
//  - log2(e) folded into q,b,f -> bare ex2.approx per rule-row (no FMUL)
//  - f and bias folded into packed accumulator inits via one LDS.128/rule
//    -> per-rule-row scalar tail is 5 instrs (2 FADD, 1 MUFU, 1 FFMA, 1 FADD)

#define A_DIM 16
#define A_PAIRS 8
#define R_RULES 64
#define BLOCK 128

typedef unsigned long long u64;

__device__ __forceinline__ u64 pack2(float lo, float hi) {
    u64 r;
    asm("mov.b64 %0, {%1, %2};" : "=l"(r) : "f"(lo), "f"(hi));
    return r;
}
__device__ __forceinline__ void unpack2(float& lo, float& hi, u64 v) {
    asm("mov.b64 {%0, %1}, %2;" : "=f"(lo), "=f"(hi) : "l"(v));
}
__device__ __forceinline__ u64 fma2(u64 a, u64 b, u64 c) {
    u64 d;
    asm("fma.rn.f32x2 %0, %1, %2, %3;" : "=l"(d) : "l"(a), "l"(b), "l"(c));
    return d;
}
__device__ __forceinline__ float exp2_approx(float v) {
    float r;
    asm("ex2.approx.ftz.f32 %0, %1;" : "=f"(r) : "f"(v));
    return r;
}

#define LOG2E 1.4426950408889634f

__global__ void __launch_bounds__(BLOCK)
fuzzy_neuron_kernel(const float* __restrict__ x,
                    const float* __restrict__ mu,
                    const float* __restrict__ sigma,
                    const float* __restrict__ rho,
                    float* __restrict__ out,
                    int n_rows) {
    // sQB [r*8+p] = {q2p, q2p+1, b2p, b2p+1}  (log2e-scaled)     8 KB
    // sRho[r*8+p] = {rho2p, rho2p+1}                             4 KB
    // sBF [r]     = {pack2(f,0), pack2(bias,0)}  (accum inits)   1 KB
    __shared__ float4 sQB[R_RULES * A_PAIRS];
    __shared__ float2 sRho[R_RULES * A_PAIRS];
    __shared__ ulonglong2 sBF[R_RULES];

    const int tid = threadIdx.x;

    for (int idx = tid; idx < R_RULES * A_PAIRS; idx += BLOCK) {
        int r = idx >> 3;
        int p = idx & (A_PAIRS - 1);
        int a0 = 2 * p;
        float m0 = mu[r * A_DIM + a0],     s0 = sigma[r * A_DIM + a0];
        float m1 = mu[r * A_DIM + a0 + 1], s1 = sigma[r * A_DIM + a0 + 1];
        float c0 = 1.0f / (2.0f * s0 * s0);
        float c1 = 1.0f / (2.0f * s1 * s1);
        sQB[idx] = make_float4(-c0 * LOG2E, -c1 * LOG2E,
                               2.0f * c0 * m0 * LOG2E, 2.0f * c1 * m1 * LOG2E);
        sRho[idx] = make_float2(rho[r * (A_DIM + 1) + a0],
                                rho[r * (A_DIM + 1) + a0 + 1]);
    }
    for (int r = tid; r < R_RULES; r += BLOCK) {
        float f = 0.0f;
        for (int a = 0; a < A_DIM; a++) {
            float m = mu[r * A_DIM + a];
            float s = sigma[r * A_DIM + a];
            f -= (m * m) / (2.0f * s * s);
        }
        sBF[r] = make_ulonglong2(pack2(f * LOG2E, 0.0f),
                                 pack2(rho[r * (A_DIM + 1) + A_DIM], 0.0f));
    }
    __syncthreads();

    // 2 rows per thread: gid and gid + n/2 (both fully coalesced).
    const int half = n_rows >> 1;
    const int gid = blockIdx.x * BLOCK + tid;
    if (gid >= half) return;
    const int row0 = gid;
    const int row1 = gid + half;

    const float4* x4 = reinterpret_cast<const float4*>(x);
    u64 xp0[A_PAIRS], xp1[A_PAIRS];
#pragma unroll
    for (int j = 0; j < 4; j++) {
        float4 v0 = x4[row0 * 4 + j];
        float4 v1 = x4[row1 * 4 + j];
        xp0[2 * j + 0] = pack2(v0.x, v0.y);
        xp0[2 * j + 1] = pack2(v0.z, v0.w);
        xp1[2 * j + 0] = pack2(v1.x, v1.y);
        xp1[2 * j + 1] = pack2(v1.z, v1.w);
    }

    float num0 = 0.0f, den0 = 0.0f, num1 = 0.0f, den1 = 0.0f;

    const float4* qb = sQB;
    const float2* rp = sRho;

#pragma unroll 2
    for (int r = 0; r < R_RULES; r++) {
        ulonglong2 bf = sBF[r];             // LDS.128: {f,0},{bias,0}
        u64 l0 = bf.x, l1 = bf.x;
        u64 z0 = bf.y, z1 = bf.y;
#pragma unroll
        for (int p = 0; p < A_PAIRS; p++) {
            float4 c = qb[p];               // LDS.128 broadcast
            float2 rr = rp[p];              // LDS.64  broadcast
            u64 q2 = pack2(c.x, c.y);
            u64 b2 = pack2(c.z, c.w);
            u64 r2 = pack2(rr.x, rr.y);
            u64 t0 = fma2(xp0[p], q2, b2);  // q*x + b
            u64 t1 = fma2(xp1[p], q2, b2);
            l0 = fma2(xp0[p], t0, l0);      // += q*x^2 + b*x
            l1 = fma2(xp1[p], t1, l1);
            z0 = fma2(xp0[p], r2, z0);      // += rho*x
            z1 = fma2(xp1[p], r2, z1);
        }
        qb += A_PAIRS;
        rp += A_PAIRS;

        float la, lb, za, zb;
        unpack2(la, lb, l0);
        unpack2(za, zb, z0);
        float w0 = exp2_approx(la + lb);    // f already in init
        float zz0 = za + zb;                // bias already in init
        num0 = fmaf(zz0, w0, num0);
        den0 += w0;

        unpack2(la, lb, l1);
        unpack2(za, zb, z1);
        float w1 = exp2_approx(la + lb);
        float zz1 = za + zb;
        num1 = fmaf(zz1, w1, num1);
        den1 += w1;
    }

    out[row0] = num0 / (den0 + 1e-13f);
    out[row1] = num1 / (den1 + 1e-13f);
}

extern "C" void kernel_launch(void* const* d_in, const int* in_sizes, int n_in,
                              void* d_out, int out_size) {
    const float* x = (const float*)d_in[0];      // [N, 16]
    const float* mu = (const float*)d_in[1];     // [64, 16]
    const float* sigma = (const float*)d_in[2];  // [64, 16]
    const float* rho = (const float*)d_in[3];    // [64, 17]
    float* out = (float*)d_out;                  // [N]

    const int n_rows = in_sizes[0] / A_DIM;      // 131072
    const int threads = n_rows / 2;
    const int blocks = (threads + BLOCK - 1) / BLOCK;

    fuzzy_neuron_kernel<<<blocks, BLOCK>>>(x, mu, sigma, rho, out, n_rows);
}

// round 4
// speedup vs baseline: 1.2000x; 1.0609x over previous
#include <cuda_runtime.h>

// FuzzyNeuron: out[n] = sum_r z[n,r]*w[n,r] / (sum_r w[n,r] + 1e-13)
//   z[n,r]    = dot(x[n], rho[r,:A]) + rho[r,A]
//   logw[n,r] = sum_a (q*x^2 + b*x) + f,  q=-1/(2s^2), b=mu/s^2, f=-sum mu^2/(2s^2)
//   (q,b,f pre-scaled by log2(e) so w = ex2.approx(logw2))
//
// R4: kill the per-rule exposed LDS latency (the 2/3 stall seen in R1-R3).
// Rule coefficients are one contiguous 13xfloat4 record; records are
// ping-ponged through two register buffers so rule r+1's LDS stream is in
// flight while rule r computes entirely from registers. 2 rows/thread,
// f32x2 over feature pairs (FMA2 pipe floor ~21K cyc/SMSP ~= 11.5us).

#define A_DIM 16
#define A_PAIRS 8
#define R_RULES 64
#define BLOCK 128

typedef unsigned long long u64;

__device__ __forceinline__ u64 pack2(float lo, float hi) {
    u64 r;
    asm("mov.b64 %0, {%1, %2};" : "=l"(r) : "f"(lo), "f"(hi));
    return r;
}
__device__ __forceinline__ void unpack2(float& lo, float& hi, u64 v) {
    asm("mov.b64 {%0, %1}, %2;" : "=f"(lo), "=f"(hi) : "l"(v));
}
__device__ __forceinline__ u64 fma2(u64 a, u64 b, u64 c) {
    u64 d;
    asm("fma.rn.f32x2 %0, %1, %2, %3;" : "=l"(d) : "l"(a), "l"(b), "l"(c));
    return d;
}
__device__ __forceinline__ float exp2_approx(float v) {
    float r;
    asm("ex2.approx.ftz.f32 %0, %1;" : "=f"(r) : "f"(v));
    return r;
}

#define LOG2E 1.4426950408889634f

// One rule's coefficients, contiguous: 13 x float4 = 208 B.
//   qb[p] = {q_{2p}, q_{2p+1}, b_{2p}, b_{2p+1}}   (log2e-scaled)
//   rh[j] = {rho_{4j} .. rho_{4j+3}}
//   fb    = {f*log2e, bias, 0, 0}
struct __align__(16) RuleCoef {
    float4 qb[A_PAIRS];
    float4 rh[4];
    float4 fb;
};

// Register-resident copy of a rule record.
struct CoefReg {
    float4 qb[A_PAIRS];
    float4 rh[4];
    float4 fb;
};

__device__ __forceinline__ void load_coef(CoefReg& c, const RuleCoef* s) {
#pragma unroll
    for (int i = 0; i < A_PAIRS; i++) c.qb[i] = s->qb[i];
#pragma unroll
    for (int i = 0; i < 4; i++) c.rh[i] = s->rh[i];
    c.fb = s->fb;
}

__device__ __forceinline__ void compute_rule(
    const CoefReg& c, const u64* __restrict__ xp0, const u64* __restrict__ xp1,
    float& num0, float& den0, float& num1, float& den1) {
    // accumulators initialized with {f,0} / {bias,0} (data already in regs)
    u64 l0 = pack2(c.fb.x, 0.0f), l1 = l0;
    u64 z0 = pack2(c.fb.y, 0.0f), z1 = z0;
#pragma unroll
    for (int p = 0; p < A_PAIRS; p++) {
        u64 q2 = pack2(c.qb[p].x, c.qb[p].y);
        u64 b2 = pack2(c.qb[p].z, c.qb[p].w);
        float4 r4 = c.rh[p >> 1];
        u64 r2 = (p & 1) ? pack2(r4.z, r4.w) : pack2(r4.x, r4.y);
        u64 t0 = fma2(xp0[p], q2, b2);   // q*x + b
        u64 t1 = fma2(xp1[p], q2, b2);
        l0 = fma2(xp0[p], t0, l0);       // += q*x^2 + b*x
        l1 = fma2(xp1[p], t1, l1);
        z0 = fma2(xp0[p], r2, z0);       // += rho*x
        z1 = fma2(xp1[p], r2, z1);
    }
    float la, lb, za, zb;
    unpack2(la, lb, l0);
    unpack2(za, zb, z0);
    float w0 = exp2_approx(la + lb);
    num0 = fmaf(za + zb, w0, num0);
    den0 += w0;
    unpack2(la, lb, l1);
    unpack2(za, zb, z1);
    float w1 = exp2_approx(la + lb);
    num1 = fmaf(za + zb, w1, num1);
    den1 += w1;
}

__global__ void __launch_bounds__(BLOCK)
fuzzy_neuron_kernel(const float* __restrict__ x,
                    const float* __restrict__ mu,
                    const float* __restrict__ sigma,
                    const float* __restrict__ rho,
                    float* __restrict__ out,
                    int n_rows) {
    __shared__ RuleCoef sC[R_RULES];   // 13.3 KB

    const int tid = threadIdx.x;

    // ---- coefficient setup ----
    for (int idx = tid; idx < R_RULES * A_PAIRS; idx += BLOCK) {
        int r = idx >> 3;
        int p = idx & (A_PAIRS - 1);
        int a0 = 2 * p;
        float m0 = mu[r * A_DIM + a0],     s0 = sigma[r * A_DIM + a0];
        float m1 = mu[r * A_DIM + a0 + 1], s1 = sigma[r * A_DIM + a0 + 1];
        float c0 = 1.0f / (2.0f * s0 * s0);
        float c1 = 1.0f / (2.0f * s1 * s1);
        sC[r].qb[p] = make_float4(-c0 * LOG2E, -c1 * LOG2E,
                                  2.0f * c0 * m0 * LOG2E, 2.0f * c1 * m1 * LOG2E);
    }
    for (int idx = tid; idx < R_RULES * 4; idx += BLOCK) {
        int r = idx >> 2;
        int j = idx & 3;
        const float* rr = &rho[r * (A_DIM + 1) + 4 * j];
        sC[r].rh[j] = make_float4(rr[0], rr[1], rr[2], rr[3]);
    }
    for (int r = tid; r < R_RULES; r += BLOCK) {
        float f = 0.0f;
        for (int a = 0; a < A_DIM; a++) {
            float m = mu[r * A_DIM + a];
            float s = sigma[r * A_DIM + a];
            f -= (m * m) / (2.0f * s * s);
        }
        sC[r].fb = make_float4(f * LOG2E, rho[r * (A_DIM + 1) + A_DIM], 0.0f, 0.0f);
    }
    __syncthreads();

    // ---- 2 rows per thread ----
    const int half = n_rows >> 1;
    const int gid = blockIdx.x * BLOCK + tid;
    if (gid >= half) return;
    const int row0 = gid;
    const int row1 = gid + half;

    const float4* x4 = reinterpret_cast<const float4*>(x);
    u64 xp0[A_PAIRS], xp1[A_PAIRS];
#pragma unroll
    for (int j = 0; j < 4; j++) {
        float4 v0 = x4[row0 * 4 + j];
        float4 v1 = x4[row1 * 4 + j];
        xp0[2 * j + 0] = pack2(v0.x, v0.y);
        xp0[2 * j + 1] = pack2(v0.z, v0.w);
        xp1[2 * j + 0] = pack2(v1.x, v1.y);
        xp1[2 * j + 1] = pack2(v1.z, v1.w);
    }

    float num0 = 0.0f, den0 = 0.0f, num1 = 0.0f, den1 = 0.0f;

    // ---- rule loop, register double-buffered (A computes while B loads) ----
    CoefReg bufA, bufB;
    load_coef(bufA, &sC[0]);
#pragma unroll 4
    for (int r = 0; r < R_RULES; r += 2) {
        load_coef(bufB, &sC[r + 1]);
        compute_rule(bufA, xp0, xp1, num0, den0, num1, den1);
        load_coef(bufA, &sC[(r + 2) & (R_RULES - 1)]);  // wraps harmlessly at end
        compute_rule(bufB, xp0, xp1, num0, den0, num1, den1);
    }

    out[row0] = num0 / (den0 + 1e-13f);
    out[row1] = num1 / (den1 + 1e-13f);
}

extern "C" void kernel_launch(void* const* d_in, const int* in_sizes, int n_in,
                              void* d_out, int out_size) {
    const float* x = (const float*)d_in[0];      // [N, 16]
    const float* mu = (const float*)d_in[1];     // [64, 16]
    const float* sigma = (const float*)d_in[2];  // [64, 16]
    const float* rho = (const float*)d_in[3];    // [64, 17]
    float* out = (float*)d_out;                  // [N]

    const int n_rows = in_sizes[0] / A_DIM;      // 131072
    const int threads = n_rows / 2;
    const int blocks = (threads + BLOCK - 1) / BLOCK;

    fuzzy_neuron_kernel<<<blocks, BLOCK>>>(x, mu, sigma, rho, out, n_rows);
}